// round 2
// baseline (speedup 1.0000x reference)
#include <cuda_runtime.h>
#include <cstdint>
#include <math.h>

#define TT 64
#define BB 64
#define EE 256
#define HH 512
#define VV 32000
#define G3 1536                      // 3H
#define KAB 768                      // H + E
#define MENC (TT*BB)                 // 4096
#define MDEC ((TT-1)*BB)             // 4032
#define BVOFF ((size_t)BB*VV)        // 2,048,000  (first timestep zeros)
#define LOSS_IDX ((size_t)TT*BB*VV)  // 131,072,000

// ---------------- scratch (static device globals; no runtime allocation) ----
__device__ float g_xg[MENC * G3];     // encoder input gates  [4096,1536]
__device__ float g_yg[MDEC * G3];     // decoder input gates  [4032,1536]
__device__ float g_A [MDEC * KAB];    // [dec_h | ey] rows for logits GEMM
__device__ float g_h [2][BB * HH];    // ping-pong hidden state
__device__ float g_lse[MDEC];         // per-row logsumexp

// ---------------- zero init: dec_out[0:B*V) and h0 --------------------------
__global__ void k_zero(float* __restrict__ dout) {
    size_t stride = (size_t)gridDim.x * blockDim.x;
    size_t total = BVOFF + (size_t)BB * HH;
    for (size_t i = (size_t)blockIdx.x * blockDim.x + threadIdx.x; i < total; i += stride) {
        if (i < BVOFF) dout[i] = 0.f;
        else           g_h[0][i - BVOFF] = 0.f;
    }
}

// ---------------- fused embedding-gather + input-gate GEMM -------------------
// out[r][c] = sum_e emb[idx[r]][e] * Wih[c][e] + bih[c]
// tiles: BM=64, BN=64, BK=32; 256 threads; 4x4 per-thread micro-tile
__global__ void k_gates(const int* __restrict__ idx,
                        const float* __restrict__ emb,
                        const float* __restrict__ Wih,
                        const float* __restrict__ bih,
                        int is_dec)
{
    __shared__ float As[32][64];
    __shared__ float Bs[32][64];
    __shared__ int   sidx[64];

    float* __restrict__ out = is_dec ? g_yg : g_xg;

    int tid = threadIdx.x;
    int r0 = blockIdx.y * 64;
    int c0 = blockIdx.x * 64;
    if (tid < 64) sidx[tid] = idx[r0 + tid];
    __syncthreads();

    int tx = tid & 15, ty = tid >> 4;
    float acc[4][4] = {};

    for (int k0 = 0; k0 < EE; k0 += 32) {
        #pragma unroll
        for (int fi = tid; fi < 512; fi += 256) {
            int r = fi >> 3, kq = (fi & 7) * 4;
            float4 v = *(const float4*)(emb + (size_t)sidx[r] * EE + k0 + kq);
            As[kq + 0][r] = v.x; As[kq + 1][r] = v.y;
            As[kq + 2][r] = v.z; As[kq + 3][r] = v.w;
        }
        #pragma unroll
        for (int fi = tid; fi < 512; fi += 256) {
            int c = fi >> 3, kq = (fi & 7) * 4;
            float4 v = *(const float4*)(Wih + (size_t)(c0 + c) * EE + k0 + kq);
            Bs[kq + 0][c] = v.x; Bs[kq + 1][c] = v.y;
            Bs[kq + 2][c] = v.z; Bs[kq + 3][c] = v.w;
        }
        __syncthreads();
        #pragma unroll
        for (int k = 0; k < 32; k++) {
            float4 a = *(const float4*)&As[k][ty * 4];
            float4 b = *(const float4*)&Bs[k][tx * 4];
            float av[4] = {a.x, a.y, a.z, a.w};
            float bv[4] = {b.x, b.y, b.z, b.w};
            #pragma unroll
            for (int i = 0; i < 4; i++)
                #pragma unroll
                for (int j = 0; j < 4; j++)
                    acc[i][j] += av[i] * bv[j];
        }
        __syncthreads();
    }

    #pragma unroll
    for (int i = 0; i < 4; i++) {
        int r = r0 + ty * 4 + i;
        #pragma unroll
        for (int j = 0; j < 4; j++) {
            int c = c0 + tx * 4 + j;
            out[(size_t)r * G3 + c] = acc[i][j] + bih[c];
        }
    }

    // decoder: also deposit ey = emb[y[r]] into A[r][H : H+E]
    if (is_dec && blockIdx.x == 0) {
        for (int q = tid; q < 64 * EE; q += 256) {
            int r = q >> 8, e = q & 255;
            g_A[(size_t)(r0 + r) * KAB + HH + e] = emb[(size_t)sidx[r] * EE + e];
        }
    }
}

// ---------------- one GRU step ----------------------------------------------
// grid 128 CTAs x 256 threads; thread = (b = tid>>2, jj = blk*4 + (tid&3))
__global__ void k_gru(int t, int is_enc,
                      const float* __restrict__ Whh,
                      const float* __restrict__ bhh,
                      const int* __restrict__ lens)
{
    int tid = threadIdx.x;
    int jj = blockIdx.x * 4 + (tid & 3);
    int b  = tid >> 2;

    const float* __restrict__ hin  = g_h[t & 1];
    float* __restrict__       hout = g_h[(t + 1) & 1];
    const float* __restrict__ xg_t = (is_enc ? g_xg : g_yg) + (size_t)t * BB * G3;

    float accR = bhh[jj];
    float accZ = bhh[jj + HH];
    float accN = bhh[jj + 2 * HH];

    const float4* h4 = (const float4*)(hin + b * HH);
    const float4* wr = (const float4*)(Whh + (size_t)jj * HH);
    const float4* wz = (const float4*)(Whh + (size_t)(jj + HH) * HH);
    const float4* wn = (const float4*)(Whh + (size_t)(jj + 2 * HH) * HH);

    #pragma unroll 4
    for (int k = 0; k < HH / 4; k++) {
        float4 h = h4[k];
        float4 r = wr[k];
        float4 z = wz[k];
        float4 n = wn[k];
        accR += h.x * r.x + h.y * r.y + h.z * r.z + h.w * r.w;
        accZ += h.x * z.x + h.y * z.y + h.z * z.z + h.w * z.w;
        accN += h.x * n.x + h.y * n.y + h.z * n.z + h.w * n.w;
    }

    size_t base = (size_t)b * G3;
    float xr = xg_t[base + jj];
    float xz = xg_t[base + jj + HH];
    float xn = xg_t[base + jj + 2 * HH];

    float rg = 1.f / (1.f + expf(-(xr + accR)));
    float zg = 1.f / (1.f + expf(-(xz + accZ)));
    float ng = tanhf(xn + rg * accN);
    float hold = hin[b * HH + jj];
    float hv = (1.f - zg) * ng + zg * hold;
    if (lens && t >= lens[b]) hv = hold;

    hout[b * HH + jj] = hv;
    if (!is_enc) g_A[(size_t)(t * BB + b) * KAB + jj] = hv;
}

// ---------------- logits GEMM: A[4032,768] x Wout[32000,768]^T + bout -------
// tiles: BM=64, BN=128, BK=16; 256 threads; 4x8 per-thread micro-tile
__global__ void k_logits(const float* __restrict__ W,
                         const float* __restrict__ bout,
                         float* __restrict__ dout)
{
    __shared__ float As[16][64];
    __shared__ float Bs[16][128];

    int tid = threadIdx.x;
    int r0 = blockIdx.y * 64;
    int c0 = blockIdx.x * 128;
    int tx = tid & 15, ty = tid >> 4;

    float acc[4][8] = {};

    for (int k0 = 0; k0 < KAB; k0 += 16) {
        {
            int r = tid >> 2, kq = (tid & 3) * 4;
            float4 v = *(const float4*)(g_A + (size_t)(r0 + r) * KAB + k0 + kq);
            As[kq + 0][r] = v.x; As[kq + 1][r] = v.y;
            As[kq + 2][r] = v.z; As[kq + 3][r] = v.w;
        }
        #pragma unroll
        for (int fi = tid; fi < 512; fi += 256) {
            int c = fi >> 2, kq = (fi & 3) * 4;
            float4 v = *(const float4*)(W + (size_t)(c0 + c) * KAB + k0 + kq);
            Bs[kq + 0][c] = v.x; Bs[kq + 1][c] = v.y;
            Bs[kq + 2][c] = v.z; Bs[kq + 3][c] = v.w;
        }
        __syncthreads();
        #pragma unroll
        for (int k = 0; k < 16; k++) {
            float4 a  = *(const float4*)&As[k][ty * 4];
            float4 b0 = *(const float4*)&Bs[k][tx * 8];
            float4 b1 = *(const float4*)&Bs[k][tx * 8 + 4];
            float av[4] = {a.x, a.y, a.z, a.w};
            float bv[8] = {b0.x, b0.y, b0.z, b0.w, b1.x, b1.y, b1.z, b1.w};
            #pragma unroll
            for (int i = 0; i < 4; i++)
                #pragma unroll
                for (int j = 0; j < 8; j++)
                    acc[i][j] += av[i] * bv[j];
        }
        __syncthreads();
    }

    float* out = dout + BVOFF;
    #pragma unroll
    for (int i = 0; i < 4; i++) {
        int row = r0 + ty * 4 + i;
        int c = c0 + tx * 8;
        float4 o0 = make_float4(acc[i][0] + bout[c + 0], acc[i][1] + bout[c + 1],
                                acc[i][2] + bout[c + 2], acc[i][3] + bout[c + 3]);
        float4 o1 = make_float4(acc[i][4] + bout[c + 4], acc[i][5] + bout[c + 5],
                                acc[i][6] + bout[c + 6], acc[i][7] + bout[c + 7]);
        *(float4*)(out + (size_t)row * VV + c)     = o0;
        *(float4*)(out + (size_t)row * VV + c + 4) = o1;
    }
}

// ---------------- per-row logsumexp over 32000 cols --------------------------
__global__ void k_lse(const float* __restrict__ dout)
{
    __shared__ float red[256];
    int row = blockIdx.x, tid = threadIdx.x;
    const float* p = dout + BVOFF + (size_t)row * VV;

    float m = -3.4e38f;
    for (int c4 = tid; c4 < VV / 4; c4 += 256) {
        float4 v = *(const float4*)(p + c4 * 4);
        m = fmaxf(m, fmaxf(fmaxf(v.x, v.y), fmaxf(v.z, v.w)));
    }
    red[tid] = m; __syncthreads();
    for (int s = 128; s; s >>= 1) {
        if (tid < s) red[tid] = fmaxf(red[tid], red[tid + s]);
        __syncthreads();
    }
    float M = red[0]; __syncthreads();

    float s = 0.f;
    for (int c4 = tid; c4 < VV / 4; c4 += 256) {
        float4 v = *(const float4*)(p + c4 * 4);
        s += __expf(v.x - M) + __expf(v.y - M) + __expf(v.z - M) + __expf(v.w - M);
    }
    red[tid] = s; __syncthreads();
    for (int st = 128; st; st >>= 1) {
        if (tid < st) red[tid] += red[tid + st];
        __syncthreads();
    }
    if (tid == 0) g_lse[row] = M + logf(red[0]);
}

// ---------------- masked NLL loss -------------------------------------------
__global__ void k_loss(const float* __restrict__ dout_r,
                       const int* __restrict__ y,
                       float* __restrict__ dout_w,
                       int has_slot)
{
    __shared__ float rs[256];
    __shared__ int   rc[256];
    int tid = threadIdx.x;
    float acc = 0.f; int cnt = 0;
    for (int r = tid; r < MDEC; r += 256) {
        int tgt = y[r + BB];                       // y[1:] flattened
        if (tgt != 0) {
            float logit = dout_r[BVOFF + (size_t)r * VV + tgt];
            acc += g_lse[r] - logit;
            cnt++;
        }
    }
    rs[tid] = acc; rc[tid] = cnt; __syncthreads();
    for (int s = 128; s; s >>= 1) {
        if (tid < s) { rs[tid] += rs[tid + s]; rc[tid] += rc[tid + s]; }
        __syncthreads();
    }
    if (tid == 0 && has_slot) dout_w[LOSS_IDX] = rs[0] / (float)max(rc[0], 1);
}

// ---------------- launch ------------------------------------------------------
extern "C" void kernel_launch(void* const* d_in, const int* in_sizes, int n_in,
                              void* d_out, int out_size)
{
    const int*   x        = (const int*)  d_in[0];
    const int*   x_lens   = (const int*)  d_in[1];
    const int*   y        = (const int*)  d_in[2];
    const float* emb      = (const float*)d_in[3];
    const float* enc_Wih  = (const float*)d_in[4];
    const float* enc_Whh  = (const float*)d_in[5];
    const float* enc_bih  = (const float*)d_in[6];
    const float* enc_bhh  = (const float*)d_in[7];
    const float* dec_Wih  = (const float*)d_in[8];
    const float* dec_Whh  = (const float*)d_in[9];
    const float* dec_bih  = (const float*)d_in[10];
    const float* dec_bhh  = (const float*)d_in[11];
    const float* Wout     = (const float*)d_in[12];
    const float* bout     = (const float*)d_in[13];
    float* out = (float*)d_out;

    (void)in_sizes; (void)n_in;

    // zeros block of dec_out + h0
    k_zero<<<1024, 256>>>(out);

    // input-gate GEMMs (+ ey deposit for decoder)
    k_gates<<<dim3(24, MENC / 64), 256>>>(x, emb, enc_Wih, enc_bih, 0);
    k_gates<<<dim3(24, MDEC / 64), 256>>>(y, emb, dec_Wih, dec_bih, 1);

    // encoder: 64 steps (length-masked)
    for (int t = 0; t < TT; t++)
        k_gru<<<128, 256>>>(t, 1, enc_Whh, enc_bhh, x_lens);

    // decoder: 63 steps (h0 = encoder final state, parity lines up: 64 is even)
    for (int t = 0; t < TT - 1; t++)
        k_gru<<<128, 256>>>(t, 0, dec_Whh, dec_bhh, (const int*)nullptr);

    // vocab projection -> dec_out[1:]
    k_logits<<<dim3(VV / 128, MDEC / 64), 256>>>(Wout, bout, out);

    // log-softmax stats + masked NLL loss
    k_lse<<<MDEC, 256>>>(out);
    int has_slot = (out_size > (int)LOSS_IDX) ? 1 : 0;
    k_loss<<<1, 256>>>(out, y, out, has_slot);
}

// round 3
// speedup vs baseline: 1.2436x; 1.2436x over previous
#include <cuda_runtime.h>
#include <cstdint>
#include <math.h>

#define TT 64
#define BB 64
#define EE 256
#define HH 512
#define VV 32000
#define G3 1536                      // 3H
#define KAB 768                      // H + E
#define MENC (TT*BB)                 // 4096
#define MDEC ((TT-1)*BB)             // 4032
#define BVOFF ((size_t)BB*VV)        // 2,048,000  (first timestep zeros)
#define LOSS_IDX ((size_t)TT*BB*VV)  // 131,072,000
#define NSTEP (2*TT - 1)             // 127 recurrent steps total
#define NCTA_GRU 128

typedef unsigned long long u64;

// ---------------- scratch (static device globals; no runtime allocation) ----
__device__ float g_xg[MENC * G3];     // encoder input gates  [4096,1536]
__device__ float g_yg[MDEC * G3];     // decoder input gates  [4032,1536]
__device__ float g_A [MDEC * KAB];    // [dec_h | ey] rows for logits GEMM
__device__ float g_h [2][BB * HH];    // ping-pong hidden state
__device__ float g_lse[MDEC];         // per-row logsumexp
__device__ unsigned g_cnt = 0;        // grid-barrier arrival counter (self-resetting)
__device__ unsigned g_gen = 0;        // grid-barrier generation (monotonic)

// ---------------- zero init: dec_out[0:B*V) and h0 --------------------------
__global__ void k_zero(float* __restrict__ dout) {
    size_t stride = (size_t)gridDim.x * blockDim.x;
    size_t total = BVOFF + (size_t)BB * HH;
    for (size_t i = (size_t)blockIdx.x * blockDim.x + threadIdx.x; i < total; i += stride) {
        if (i < BVOFF) dout[i] = 0.f;
        else           g_h[0][i - BVOFF] = 0.f;
    }
}

// ---------------- fused embedding-gather + input-gate GEMM -------------------
__global__ void k_gates(const int* __restrict__ idx,
                        const float* __restrict__ emb,
                        const float* __restrict__ Wih,
                        const float* __restrict__ bih,
                        int is_dec)
{
    __shared__ float As[32][64];
    __shared__ float Bs[32][64];
    __shared__ int   sidx[64];

    float* __restrict__ out = is_dec ? g_yg : g_xg;

    int tid = threadIdx.x;
    int r0 = blockIdx.y * 64;
    int c0 = blockIdx.x * 64;
    if (tid < 64) sidx[tid] = idx[r0 + tid];
    __syncthreads();

    int tx = tid & 15, ty = tid >> 4;
    float acc[4][4] = {};

    for (int k0 = 0; k0 < EE; k0 += 32) {
        #pragma unroll
        for (int fi = tid; fi < 512; fi += 256) {
            int r = fi >> 3, kq = (fi & 7) * 4;
            float4 v = *(const float4*)(emb + (size_t)sidx[r] * EE + k0 + kq);
            As[kq + 0][r] = v.x; As[kq + 1][r] = v.y;
            As[kq + 2][r] = v.z; As[kq + 3][r] = v.w;
        }
        #pragma unroll
        for (int fi = tid; fi < 512; fi += 256) {
            int c = fi >> 3, kq = (fi & 7) * 4;
            float4 v = *(const float4*)(Wih + (size_t)(c0 + c) * EE + k0 + kq);
            Bs[kq + 0][c] = v.x; Bs[kq + 1][c] = v.y;
            Bs[kq + 2][c] = v.z; Bs[kq + 3][c] = v.w;
        }
        __syncthreads();
        #pragma unroll
        for (int k = 0; k < 32; k++) {
            float4 a = *(const float4*)&As[k][ty * 4];
            float4 b = *(const float4*)&Bs[k][tx * 4];
            float av[4] = {a.x, a.y, a.z, a.w};
            float bv[4] = {b.x, b.y, b.z, b.w};
            #pragma unroll
            for (int i = 0; i < 4; i++)
                #pragma unroll
                for (int j = 0; j < 4; j++)
                    acc[i][j] += av[i] * bv[j];
        }
        __syncthreads();
    }

    #pragma unroll
    for (int i = 0; i < 4; i++) {
        int r = r0 + ty * 4 + i;
        #pragma unroll
        for (int j = 0; j < 4; j++) {
            int c = c0 + tx * 4 + j;
            out[(size_t)r * G3 + c] = acc[i][j] + bih[c];
        }
    }

    if (is_dec && blockIdx.x == 0) {
        for (int q = tid; q < 64 * EE; q += 256) {
            int r = q >> 8, e = q & 255;
            g_A[(size_t)(r0 + r) * KAB + HH + e] = emb[(size_t)sidx[r] * EE + e];
        }
    }
}

// ---------------- persistent fused GRU (all 127 steps, one launch) ----------
#define FMA2(acc, a, b) asm("fma.rn.f32x2 %0, %1, %2, %0;" : "+l"(acc) : "l"(a), "l"(b))

__device__ __forceinline__ float hsum2(u64 v) {
    float lo = __uint_as_float((unsigned)(v & 0xffffffffull));
    float hi = __uint_as_float((unsigned)(v >> 32));
    return lo + hi;
}

__device__ __forceinline__ void load_whh(float w_s[3][4][516], const float* __restrict__ Whh,
                                         int jbase, int tid)
{
    // 1536 float4 = 6144 floats; 256 threads x 6 float4
    for (int i = tid; i < 1536; i += 256) {
        int g  = i >> 9;          // /512
        int jj = (i >> 7) & 3;    // 128 float4 per row
        int k4 = i & 127;
        float4 v = *(const float4*)(Whh + ((size_t)(g * HH + jbase + jj)) * HH + k4 * 4);
        *(float4*)&w_s[g][jj][k4 * 4] = v;
    }
}

__global__ void __launch_bounds__(256, 1)
k_gru_persist(const float* __restrict__ enc_Whh, const float* __restrict__ enc_bhh,
              const float* __restrict__ dec_Whh, const float* __restrict__ dec_bhh,
              const int*   __restrict__ lens)
{
    __shared__ float w_s[3][4][516];   // padded: 516 % 32 = 4 -> conflict-free LDS

    int tid = threadIdx.x;
    int jl  = tid & 3;
    int b   = tid >> 2;
    int jbase = blockIdx.x * 4;
    int j   = jbase + jl;

    unsigned base_gen = 0;
    if (tid == 0) base_gen = *((volatile unsigned*)&g_gen);   // re-base per launch (graph replays)

    int lenb = lens[b];

    load_whh(w_s, enc_Whh, jbase, tid);
    __syncthreads();

    const float* bhh = enc_bhh;

    for (int s = 0; s < NSTEP; s++) {
        if (s == TT) {                       // switch to decoder weights
            load_whh(w_s, dec_Whh, jbase, tid);
            bhh = dec_bhh;
            __syncthreads();
        }

        const float* __restrict__ hin  = g_h[s & 1];
        float* __restrict__       hout = g_h[(s + 1) & 1];
        const float* __restrict__ xg   = (s < TT)
            ? g_xg + (size_t)s * BB * G3
            : g_yg + (size_t)(s - TT) * BB * G3;

        const ulonglong2* __restrict__ h2  = (const ulonglong2*)(hin + (size_t)b * HH);
        const ulonglong2* __restrict__ wr2 = (const ulonglong2*)&w_s[0][jl][0];
        const ulonglong2* __restrict__ wz2 = (const ulonglong2*)&w_s[1][jl][0];
        const ulonglong2* __restrict__ wn2 = (const ulonglong2*)&w_s[2][jl][0];

        u64 aR0 = 0, aR1 = 0, aZ0 = 0, aZ1 = 0, aN0 = 0, aN1 = 0;
        #pragma unroll 8
        for (int k4 = 0; k4 < HH / 4; k4++) {
            ulonglong2 h = h2[k4];
            ulonglong2 r = wr2[k4];
            ulonglong2 z = wz2[k4];
            ulonglong2 n = wn2[k4];
            FMA2(aR0, h.x, r.x); FMA2(aR1, h.y, r.y);
            FMA2(aZ0, h.x, z.x); FMA2(aZ1, h.y, z.y);
            FMA2(aN0, h.x, n.x); FMA2(aN1, h.y, n.y);
        }
        float accR = bhh[j]          + hsum2(aR0) + hsum2(aR1);
        float accZ = bhh[j + HH]     + hsum2(aZ0) + hsum2(aZ1);
        float accN = bhh[j + 2 * HH] + hsum2(aN0) + hsum2(aN1);

        size_t xb = (size_t)b * G3;
        float xr = xg[xb + j];
        float xz = xg[xb + j + HH];
        float xn = xg[xb + j + 2 * HH];

        float rg = 1.f / (1.f + expf(-(xr + accR)));
        float zg = 1.f / (1.f + expf(-(xz + accZ)));
        float ng = tanhf(xn + rg * accN);
        float hold = hin[(size_t)b * HH + j];
        float hv = (1.f - zg) * ng + zg * hold;
        if (s < TT && s >= lenb) hv = hold;      // encoder length mask

        hout[(size_t)b * HH + j] = hv;
        if (s >= TT) g_A[((size_t)(s - TT) * BB + b) * KAB + j] = hv;

        // ---- software grid barrier (skip after final step) ----
        if (s == NSTEP - 1) break;
        __threadfence();
        __syncthreads();
        if (tid == 0) {
            unsigned target = base_gen + (unsigned)(s + 1);
            if (atomicAdd(&g_cnt, 1u) == (unsigned)(gridDim.x - 1)) {
                g_cnt = 0;
                asm volatile("st.release.gpu.u32 [%0], %1;" :: "l"(&g_gen), "r"(target) : "memory");
            } else {
                unsigned v;
                do {
                    asm volatile("ld.acquire.gpu.u32 %0, [%1];" : "=r"(v) : "l"(&g_gen) : "memory");
                } while ((int)(v - target) < 0);
            }
        }
        __syncthreads();
    }
}

// ---------------- logits GEMM: A[4032,768] x Wout[32000,768]^T + bout -------
__global__ void k_logits(const float* __restrict__ W,
                         const float* __restrict__ bout,
                         float* __restrict__ dout)
{
    __shared__ float As[16][64];
    __shared__ float Bs[16][128];

    int tid = threadIdx.x;
    int r0 = blockIdx.y * 64;
    int c0 = blockIdx.x * 128;
    int tx = tid & 15, ty = tid >> 4;

    float acc[4][8] = {};

    for (int k0 = 0; k0 < KAB; k0 += 16) {
        {
            int r = tid >> 2, kq = (tid & 3) * 4;
            float4 v = *(const float4*)(g_A + (size_t)(r0 + r) * KAB + k0 + kq);
            As[kq + 0][r] = v.x; As[kq + 1][r] = v.y;
            As[kq + 2][r] = v.z; As[kq + 3][r] = v.w;
        }
        #pragma unroll
        for (int fi = tid; fi < 512; fi += 256) {
            int c = fi >> 2, kq = (fi & 3) * 4;
            float4 v = *(const float4*)(W + (size_t)(c0 + c) * KAB + k0 + kq);
            Bs[kq + 0][c] = v.x; Bs[kq + 1][c] = v.y;
            Bs[kq + 2][c] = v.z; Bs[kq + 3][c] = v.w;
        }
        __syncthreads();
        #pragma unroll
        for (int k = 0; k < 16; k++) {
            float4 a  = *(const float4*)&As[k][ty * 4];
            float4 b0 = *(const float4*)&Bs[k][tx * 8];
            float4 b1 = *(const float4*)&Bs[k][tx * 8 + 4];
            float av[4] = {a.x, a.y, a.z, a.w};
            float bv[8] = {b0.x, b0.y, b0.z, b0.w, b1.x, b1.y, b1.z, b1.w};
            #pragma unroll
            for (int i = 0; i < 4; i++)
                #pragma unroll
                for (int jx = 0; jx < 8; jx++)
                    acc[i][jx] += av[i] * bv[jx];
        }
        __syncthreads();
    }

    float* out = dout + BVOFF;
    #pragma unroll
    for (int i = 0; i < 4; i++) {
        int row = r0 + ty * 4 + i;
        int c = c0 + tx * 8;
        float4 o0 = make_float4(acc[i][0] + bout[c + 0], acc[i][1] + bout[c + 1],
                                acc[i][2] + bout[c + 2], acc[i][3] + bout[c + 3]);
        float4 o1 = make_float4(acc[i][4] + bout[c + 4], acc[i][5] + bout[c + 5],
                                acc[i][6] + bout[c + 6], acc[i][7] + bout[c + 7]);
        *(float4*)(out + (size_t)row * VV + c)     = o0;
        *(float4*)(out + (size_t)row * VV + c + 4) = o1;
    }
}

// ---------------- per-row logsumexp over 32000 cols --------------------------
__global__ void k_lse(const float* __restrict__ dout)
{
    __shared__ float red[256];
    int row = blockIdx.x, tid = threadIdx.x;
    const float* p = dout + BVOFF + (size_t)row * VV;

    float m = -3.4e38f;
    for (int c4 = tid; c4 < VV / 4; c4 += 256) {
        float4 v = *(const float4*)(p + c4 * 4);
        m = fmaxf(m, fmaxf(fmaxf(v.x, v.y), fmaxf(v.z, v.w)));
    }
    red[tid] = m; __syncthreads();
    for (int s = 128; s; s >>= 1) {
        if (tid < s) red[tid] = fmaxf(red[tid], red[tid + s]);
        __syncthreads();
    }
    float M = red[0]; __syncthreads();

    float s = 0.f;
    for (int c4 = tid; c4 < VV / 4; c4 += 256) {
        float4 v = *(const float4*)(p + c4 * 4);
        s += __expf(v.x - M) + __expf(v.y - M) + __expf(v.z - M) + __expf(v.w - M);
    }
    red[tid] = s; __syncthreads();
    for (int st = 128; st; st >>= 1) {
        if (tid < st) red[tid] += red[tid + st];
        __syncthreads();
    }
    if (tid == 0) g_lse[row] = M + logf(red[0]);
}

// ---------------- masked NLL loss -------------------------------------------
__global__ void k_loss(const float* __restrict__ dout_r,
                       const int* __restrict__ y,
                       float* __restrict__ dout_w,
                       int has_slot)
{
    __shared__ float rs[256];
    __shared__ int   rc[256];
    int tid = threadIdx.x;
    float acc = 0.f; int cnt = 0;
    for (int r = tid; r < MDEC; r += 256) {
        int tgt = y[r + BB];
        if (tgt != 0) {
            float logit = dout_r[BVOFF + (size_t)r * VV + tgt];
            acc += g_lse[r] - logit;
            cnt++;
        }
    }
    rs[tid] = acc; rc[tid] = cnt; __syncthreads();
    for (int s = 128; s; s >>= 1) {
        if (tid < s) { rs[tid] += rs[tid + s]; rc[tid] += rc[tid + s]; }
        __syncthreads();
    }
    if (tid == 0 && has_slot) dout_w[LOSS_IDX] = rs[0] / (float)max(rc[0], 1);
}

// ---------------- launch ------------------------------------------------------
extern "C" void kernel_launch(void* const* d_in, const int* in_sizes, int n_in,
                              void* d_out, int out_size)
{
    const int*   x        = (const int*)  d_in[0];
    const int*   x_lens   = (const int*)  d_in[1];
    const int*   y        = (const int*)  d_in[2];
    const float* emb      = (const float*)d_in[3];
    const float* enc_Wih  = (const float*)d_in[4];
    const float* enc_Whh  = (const float*)d_in[5];
    const float* enc_bih  = (const float*)d_in[6];
    const float* enc_bhh  = (const float*)d_in[7];
    const float* dec_Wih  = (const float*)d_in[8];
    const float* dec_Whh  = (const float*)d_in[9];
    const float* dec_bih  = (const float*)d_in[10];
    const float* dec_bhh  = (const float*)d_in[11];
    const float* Wout     = (const float*)d_in[12];
    const float* bout     = (const float*)d_in[13];
    float* out = (float*)d_out;

    (void)in_sizes; (void)n_in;

    k_zero<<<1024, 256>>>(out);

    k_gates<<<dim3(24, MENC / 64), 256>>>(x, emb, enc_Wih, enc_bih, 0);
    k_gates<<<dim3(24, MDEC / 64), 256>>>(y, emb, dec_Wih, dec_bih, 1);

    // all 127 recurrent steps in one persistent launch
    k_gru_persist<<<NCTA_GRU, 256>>>(enc_Whh, enc_bhh, dec_Whh, dec_bhh, x_lens);

    k_logits<<<dim3(VV / 128, MDEC / 64), 256>>>(Wout, bout, out);

    k_lse<<<MDEC, 256>>>(out);
    int has_slot = (out_size > (int)LOSS_IDX) ? 1 : 0;
    k_loss<<<1, 256>>>(out, y, out, has_slot);
}

// round 8
// speedup vs baseline: 4.1897x; 3.3691x over previous
#include <cuda_runtime.h>
#include <cuda_fp16.h>
#include <mma.h>
#include <cstdint>
#include <math.h>

using namespace nvcuda;

#define TT 64
#define BB 64
#define EE 256
#define HH 512
#define VV 32000
#define G3 1536                      // 3H
#define KAB 768                      // H + E
#define MENC (TT*BB)                 // 4096
#define MDEC ((TT-1)*BB)             // 4032
#define MPAD 4096                    // padded rows for 128-row M tiles
#define BVOFF ((size_t)BB*VV)        // 2,048,000  (first timestep zeros)
#define LOSS_IDX ((size_t)TT*BB*VV)  // 131,072,000
#define NSTEP (2*TT - 1)             // 127 recurrent steps
#define NCTA_GRU 128

typedef unsigned long long u64;

// ---------------- scratch (static device globals; no runtime allocation) ----
__device__ float g_xg[MENC * G3];              // encoder input gates
__device__ float g_yg[MDEC * G3];              // decoder input gates
__device__ __align__(256) __half g_Ah[MPAD * KAB];   // [dec_h | ey] as fp16
__device__ __align__(256) __half g_Wh[VV * KAB];     // Wout as fp16
__device__ float g_h [2][BB * HH];             // ping-pong hidden state
__device__ float g_lse[MDEC];                  // per-row logsumexp
__device__ unsigned g_cnt = 0;                 // grid-barrier counter
__device__ unsigned g_gen = 0;                 // grid-barrier generation

// ================= helpers ===================================================
__device__ __forceinline__ uint32_t smem_u32(const void* p) {
    uint32_t a;
    asm("{ .reg .u64 t; cvta.to.shared.u64 t, %1; cvt.u32.u64 %0, t; }" : "=r"(a) : "l"(p));
    return a;
}
__device__ __forceinline__ void cp_async16(uint32_t dst, const void* src) {
    asm volatile("cp.async.cg.shared.global [%0], [%1], 16;" :: "r"(dst), "l"(src));
}
#define CP_COMMIT() asm volatile("cp.async.commit_group;" ::: "memory")

// ---------------- zero init: dec_out[0:B*V), h0, g_Ah pad rows ---------------
__global__ void k_zero(float* __restrict__ dout) {
    size_t stride = (size_t)gridDim.x * blockDim.x;
    size_t t1 = BVOFF;
    size_t t2 = t1 + (size_t)BB * HH;
    size_t t3 = t2 + (size_t)(MPAD - MDEC) * KAB / 2;   // pad rows as uint words
    for (size_t i = (size_t)blockIdx.x * blockDim.x + threadIdx.x; i < t3; i += stride) {
        if (i < t1)      dout[i] = 0.f;
        else if (i < t2) g_h[0][i - t1] = 0.f;
        else ((unsigned*)(g_Ah + (size_t)MDEC * KAB))[i - t2] = 0u;
    }
}

// ---------------- Wout fp32 -> fp16 ------------------------------------------
__global__ void k_convW(const float* __restrict__ W) {
    size_t i = ((size_t)blockIdx.x * blockDim.x + threadIdx.x) * 8;
    if (i >= (size_t)VV * KAB) return;
    float4 a = *(const float4*)(W + i);
    float4 b = *(const float4*)(W + i + 4);
    __half2 h0 = __floats2half2_rn(a.x, a.y);
    __half2 h1 = __floats2half2_rn(a.z, a.w);
    __half2 h2 = __floats2half2_rn(b.x, b.y);
    __half2 h3 = __floats2half2_rn(b.z, b.w);
    uint4 o;
    o.x = *(uint32_t*)&h0; o.y = *(uint32_t*)&h1;
    o.z = *(uint32_t*)&h2; o.w = *(uint32_t*)&h3;
    *(uint4*)(g_Wh + i) = o;
}

// ---------------- fused embedding-gather + input-gate GEMM -------------------
__global__ void k_gates(const int* __restrict__ idx,
                        const float* __restrict__ emb,
                        const float* __restrict__ Wih,
                        const float* __restrict__ bih,
                        int is_dec)
{
    __shared__ float As[32][64];
    __shared__ float Bs[32][64];
    __shared__ int   sidx[64];

    float* __restrict__ out = is_dec ? g_yg : g_xg;

    int tid = threadIdx.x;
    int r0 = blockIdx.y * 64;
    int c0 = blockIdx.x * 64;
    if (tid < 64) sidx[tid] = idx[r0 + tid];
    __syncthreads();

    int tx = tid & 15, ty = tid >> 4;
    float acc[4][4] = {};

    for (int k0 = 0; k0 < EE; k0 += 32) {
        #pragma unroll
        for (int fi = tid; fi < 512; fi += 256) {
            int r = fi >> 3, kq = (fi & 7) * 4;
            float4 v = *(const float4*)(emb + (size_t)sidx[r] * EE + k0 + kq);
            As[kq + 0][r] = v.x; As[kq + 1][r] = v.y;
            As[kq + 2][r] = v.z; As[kq + 3][r] = v.w;
        }
        #pragma unroll
        for (int fi = tid; fi < 512; fi += 256) {
            int c = fi >> 3, kq = (fi & 7) * 4;
            float4 v = *(const float4*)(Wih + (size_t)(c0 + c) * EE + k0 + kq);
            Bs[kq + 0][c] = v.x; Bs[kq + 1][c] = v.y;
            Bs[kq + 2][c] = v.z; Bs[kq + 3][c] = v.w;
        }
        __syncthreads();
        #pragma unroll
        for (int k = 0; k < 32; k++) {
            float4 a = *(const float4*)&As[k][ty * 4];
            float4 b = *(const float4*)&Bs[k][tx * 4];
            float av[4] = {a.x, a.y, a.z, a.w};
            float bv[4] = {b.x, b.y, b.z, b.w};
            #pragma unroll
            for (int i = 0; i < 4; i++)
                #pragma unroll
                for (int j = 0; j < 4; j++)
                    acc[i][j] += av[i] * bv[j];
        }
        __syncthreads();
    }

    #pragma unroll
    for (int i = 0; i < 4; i++) {
        int r = r0 + ty * 4 + i;
        #pragma unroll
        for (int j = 0; j < 4; j++) {
            int c = c0 + tx * 4 + j;
            out[(size_t)r * G3 + c] = acc[i][j] + bih[c];
        }
    }

    if (is_dec && blockIdx.x == 0) {
        for (int q = tid; q < 64 * EE; q += 256) {
            int r = q >> 8, e = q & 255;
            g_Ah[(size_t)(r0 + r) * KAB + HH + e] =
                __float2half_rn(emb[(size_t)sidx[r] * EE + e]);
        }
    }
}

// ---------------- persistent fused GRU (all 127 steps) -----------------------
#define FMA2(acc, a, b) asm("fma.rn.f32x2 %0, %1, %2, %0;" : "+l"(acc) : "l"(a), "l"(b))
__device__ __forceinline__ float hsum2(u64 v) {
    float lo = __uint_as_float((unsigned)(v & 0xffffffffull));
    float hi = __uint_as_float((unsigned)(v >> 32));
    return lo + hi;
}

#define WROW 516                          // padded row (conflict-free)
#define GRU_SMEM ((3*4*WROW + BB*WROW) * 4)   // 156,864 B

__device__ __forceinline__ void load_whh(float* w_s, const float* __restrict__ Whh,
                                         int jbase, int tid)
{
    for (int i = tid; i < 1536; i += 256) {
        int g  = i >> 9;
        int jj = (i >> 7) & 3;
        int k4 = i & 127;
        float4 v = *(const float4*)(Whh + ((size_t)(g * HH + jbase + jj)) * HH + k4 * 4);
        *(float4*)&w_s[((g * 4 + jj) * WROW) + k4 * 4] = v;
    }
}

__global__ void __launch_bounds__(256, 1)
k_gru_persist(const float* __restrict__ enc_Whh, const float* __restrict__ enc_bhh,
              const float* __restrict__ dec_Whh, const float* __restrict__ dec_bhh,
              const int*   __restrict__ lens)
{
    extern __shared__ float sm[];
    float* w_s = sm;                      // [3][4][WROW]
    float* h_s = sm + 3 * 4 * WROW;       // [64][WROW]

    int tid = threadIdx.x;
    int jl  = tid & 3;
    int b   = tid >> 2;
    int jbase = blockIdx.x * 4;
    int j   = jbase + jl;

    unsigned base_gen = 0;
    if (tid == 0) base_gen = *((volatile unsigned*)&g_gen);

    int lenb = lens[b];

    load_whh(w_s, enc_Whh, jbase, tid);
    const float* bhh = enc_bhh;

    for (int s = 0; s < NSTEP; s++) {
        if (s == TT) { load_whh(w_s, dec_Whh, jbase, tid); bhh = dec_bhh; }

        const float* __restrict__ hin  = g_h[s & 1];
        float* __restrict__       hout = g_h[(s + 1) & 1];
        const float* __restrict__ xg   = (s < TT)
            ? g_xg + (size_t)s * BB * G3
            : g_yg + (size_t)(s - TT) * BB * G3;

        // stage full h into smem (coalesced)
        {
            const float4* hin4 = (const float4*)hin;
            for (int i = tid; i < BB * HH / 4; i += 256) {
                float4 v = hin4[i];
                int bb = i >> 7, k4 = i & 127;
                *(float4*)&h_s[bb * WROW + k4 * 4] = v;
            }
        }
        __syncthreads();

        const ulonglong2* __restrict__ h2  = (const ulonglong2*)&h_s[b * WROW];
        const ulonglong2* __restrict__ wr2 = (const ulonglong2*)&w_s[(0 * 4 + jl) * WROW];
        const ulonglong2* __restrict__ wz2 = (const ulonglong2*)&w_s[(1 * 4 + jl) * WROW];
        const ulonglong2* __restrict__ wn2 = (const ulonglong2*)&w_s[(2 * 4 + jl) * WROW];

        u64 aR0 = 0, aR1 = 0, aZ0 = 0, aZ1 = 0, aN0 = 0, aN1 = 0;
        #pragma unroll 8
        for (int k4 = 0; k4 < HH / 4; k4++) {
            ulonglong2 h = h2[k4];
            ulonglong2 r = wr2[k4];
            ulonglong2 z = wz2[k4];
            ulonglong2 n = wn2[k4];
            FMA2(aR0, h.x, r.x); FMA2(aR1, h.y, r.y);
            FMA2(aZ0, h.x, z.x); FMA2(aZ1, h.y, z.y);
            FMA2(aN0, h.x, n.x); FMA2(aN1, h.y, n.y);
        }
        float accR = bhh[j]          + hsum2(aR0) + hsum2(aR1);
        float accZ = bhh[j + HH]     + hsum2(aZ0) + hsum2(aZ1);
        float accN = bhh[j + 2 * HH] + hsum2(aN0) + hsum2(aN1);

        size_t xb = (size_t)b * G3;
        float xr = xg[xb + j];
        float xz = xg[xb + j + HH];
        float xn = xg[xb + j + 2 * HH];

        float rg = 1.f / (1.f + expf(-(xr + accR)));
        float zg = 1.f / (1.f + expf(-(xz + accZ)));
        float ng = tanhf(xn + rg * accN);
        float hold = h_s[b * WROW + j];
        float hv = (1.f - zg) * ng + zg * hold;
        if (s < TT && s >= lenb) hv = hold;

        hout[(size_t)b * HH + j] = hv;
        if (s >= TT) g_Ah[((size_t)(s - TT) * BB + b) * KAB + j] = __float2half_rn(hv);

        if (s == NSTEP - 1) break;
        __threadfence();
        __syncthreads();
        if (tid == 0) {
            unsigned target = base_gen + (unsigned)(s + 1);
            if (atomicAdd(&g_cnt, 1u) == (unsigned)(gridDim.x - 1)) {
                g_cnt = 0;
                asm volatile("st.release.gpu.u32 [%0], %1;" :: "l"(&g_gen), "r"(target) : "memory");
            } else {
                unsigned v;
                do {
                    asm volatile("ld.acquire.gpu.u32 %0, [%1];" : "=r"(v) : "l"(&g_gen) : "memory");
                } while ((int)(v - target) < 0);
            }
        }
        __syncthreads();
    }
}

// ---------------- logits via wmma (HMMA, base-target safe) -------------------
// D[4096,32000] = Ah[4096,768] x Wh[32000,768]^T + bout
// CTA 128x128, K-chunks of 64, double-buffered cp.async; 8 warps x (64x32) tile
#define LDSH 72                            // smem row stride in halves (16B-mult, ldsm conflict-free)
#define STAGE_H (128 * LDSH)               // halves per matrix per stage
#define NCHUNK 12
#define LOGITS_SMEM (1024 + 4 * STAGE_H * 2)   // 2 stages x (A+B), +1K align slack

__device__ __forceinline__ void load_chunk_l(int ck, __half* dA, __half* dB,
                                             int m0, int n0, int tid)
{
    uint32_t a32 = smem_u32(dA), b32 = smem_u32(dB);
    const char* Ab = (const char*)g_Ah;
    const char* Bb = (const char*)g_Wh;
    size_t koff = (size_t)ck * 64 * 2;        // bytes
    #pragma unroll
    for (int i = 0; i < 4; i++) {             // A: 128 rows x 64 halves
        int idx = tid + i * 256;
        int r = idx >> 3, cb = idx & 7;
        cp_async16(a32 + (r * LDSH + cb * 8) * 2,
                   Ab + ((size_t)(m0 + r) * KAB) * 2 + koff + cb * 16);
    }
    #pragma unroll
    for (int i = 0; i < 4; i++) {             // B: 128 rows x 64 halves
        int idx = tid + i * 256;
        int r = idx >> 3, cb = idx & 7;
        cp_async16(b32 + (r * LDSH + cb * 8) * 2,
                   Bb + ((size_t)(n0 + r) * KAB) * 2 + koff + cb * 16);
    }
}

__global__ void __launch_bounds__(256, 2)
k_logits_mma(const float* __restrict__ bout, float* __restrict__ dout)
{
    extern __shared__ char smraw[];
    __shared__ float bias_s[128];

    uint32_t sb0 = smem_u32(smraw);
    uint32_t sb  = (sb0 + 1023) & ~1023u;
    __half* smh = (__half*)(smraw + (sb - sb0));
    __half* Abuf[2] = { smh,               smh + 2 * STAGE_H };
    __half* Bbuf[2] = { smh + STAGE_H,     smh + 3 * STAGE_H };

    int tid = threadIdx.x, wid = tid >> 5;
    int n0 = blockIdx.x * 128;
    int m0 = blockIdx.y * 128;
    int wm = wid & 1;        // 2 warps over M (64 rows each)
    int wn = wid >> 1;       // 4 warps over N (32 cols each)

    if (tid < 128) bias_s[tid] = bout[n0 + tid];

    wmma::fragment<wmma::accumulator, 16, 16, 16, float> acc[4][2];
    #pragma unroll
    for (int i = 0; i < 4; i++)
        #pragma unroll
        for (int j = 0; j < 2; j++) wmma::fill_fragment(acc[i][j], 0.f);

    load_chunk_l(0, Abuf[0], Bbuf[0], m0, n0, tid);
    CP_COMMIT();

    for (int c = 0; c < NCHUNK; c++) {
        if (c + 1 < NCHUNK) {
            load_chunk_l(c + 1, Abuf[(c + 1) & 1], Bbuf[(c + 1) & 1], m0, n0, tid);
            CP_COMMIT();
            asm volatile("cp.async.wait_group 1;" ::: "memory");
        } else {
            asm volatile("cp.async.wait_group 0;" ::: "memory");
        }
        __syncthreads();

        const __half* Ab = Abuf[c & 1];
        const __half* Bb = Bbuf[c & 1];
        #pragma unroll
        for (int k = 0; k < 4; k++) {
            wmma::fragment<wmma::matrix_a, 16, 16, 16, __half, wmma::row_major> af[4];
            wmma::fragment<wmma::matrix_b, 16, 16, 16, __half, wmma::col_major> bf[2];
            #pragma unroll
            for (int mi = 0; mi < 4; mi++)
                wmma::load_matrix_sync(af[mi], Ab + (wm * 64 + mi * 16) * LDSH + k * 16, LDSH);
            #pragma unroll
            for (int ni = 0; ni < 2; ni++)
                wmma::load_matrix_sync(bf[ni], Bb + (wn * 32 + ni * 16) * LDSH + k * 16, LDSH);
            #pragma unroll
            for (int mi = 0; mi < 4; mi++)
                #pragma unroll
                for (int ni = 0; ni < 2; ni++)
                    wmma::mma_sync(acc[mi][ni], af[mi], bf[ni], acc[mi][ni]);
        }
        __syncthreads();
    }

    // epilogue: stage C in smem (reuse stage buffers), then bias + guarded store
    float* C = (float*)smh;                 // [128][132]
    #pragma unroll
    for (int mi = 0; mi < 4; mi++)
        #pragma unroll
        for (int ni = 0; ni < 2; ni++)
            wmma::store_matrix_sync(C + (wm * 64 + mi * 16) * 132 + wn * 32 + ni * 16,
                                    acc[mi][ni], 132, wmma::mem_row_major);
    __syncthreads();

    float* outb = dout + BVOFF;
    #pragma unroll
    for (int i = 0; i < 16; i++) {
        int idx = tid + i * 256;
        int r = idx >> 5, c4 = (idx & 31) * 4;
        int row = m0 + r;
        if (row < MDEC) {
            float4 v;
            v.x = C[r * 132 + c4 + 0] + bias_s[c4 + 0];
            v.y = C[r * 132 + c4 + 1] + bias_s[c4 + 1];
            v.z = C[r * 132 + c4 + 2] + bias_s[c4 + 2];
            v.w = C[r * 132 + c4 + 3] + bias_s[c4 + 3];
            *(float4*)(outb + (size_t)row * VV + n0 + c4) = v;
        }
    }
}

// ---------------- per-row logsumexp over 32000 cols --------------------------
__global__ void k_lse(const float* __restrict__ dout)
{
    __shared__ float red[256];
    int row = blockIdx.x, tid = threadIdx.x;
    const float* p = dout + BVOFF + (size_t)row * VV;

    float m = -3.4e38f;
    for (int c4 = tid; c4 < VV / 4; c4 += 256) {
        float4 v = *(const float4*)(p + c4 * 4);
        m = fmaxf(m, fmaxf(fmaxf(v.x, v.y), fmaxf(v.z, v.w)));
    }
    red[tid] = m; __syncthreads();
    for (int s = 128; s; s >>= 1) {
        if (tid < s) red[tid] = fmaxf(red[tid], red[tid + s]);
        __syncthreads();
    }
    float M = red[0]; __syncthreads();

    float s = 0.f;
    for (int c4 = tid; c4 < VV / 4; c4 += 256) {
        float4 v = *(const float4*)(p + c4 * 4);
        s += __expf(v.x - M) + __expf(v.y - M) + __expf(v.z - M) + __expf(v.w - M);
    }
    red[tid] = s; __syncthreads();
    for (int st = 128; st; st >>= 1) {
        if (tid < st) red[tid] += red[tid + st];
        __syncthreads();
    }
    if (tid == 0) g_lse[row] = M + logf(red[0]);
}

// ---------------- masked NLL loss -------------------------------------------
__global__ void k_loss(const float* __restrict__ dout_r,
                       const int* __restrict__ y,
                       float* __restrict__ dout_w,
                       int has_slot)
{
    __shared__ float rs[256];
    __shared__ int   rc[256];
    int tid = threadIdx.x;
    float acc = 0.f; int cnt = 0;
    for (int r = tid; r < MDEC; r += 256) {
        int tgt = y[r + BB];
        if (tgt != 0) {
            float logit = dout_r[BVOFF + (size_t)r * VV + tgt];
            acc += g_lse[r] - logit;
            cnt++;
        }
    }
    rs[tid] = acc; rc[tid] = cnt; __syncthreads();
    for (int s = 128; s; s >>= 1) {
        if (tid < s) { rs[tid] += rs[tid + s]; rc[tid] += rc[tid + s]; }
        __syncthreads();
    }
    if (tid == 0 && has_slot) dout_w[LOSS_IDX] = rs[0] / (float)max(rc[0], 1);
}

// ---------------- launch ------------------------------------------------------
extern "C" void kernel_launch(void* const* d_in, const int* in_sizes, int n_in,
                              void* d_out, int out_size)
{
    const int*   x        = (const int*)  d_in[0];
    const int*   x_lens   = (const int*)  d_in[1];
    const int*   y        = (const int*)  d_in[2];
    const float* emb      = (const float*)d_in[3];
    const float* enc_Wih  = (const float*)d_in[4];
    const float* enc_Whh  = (const float*)d_in[5];
    const float* enc_bih  = (const float*)d_in[6];
    const float* enc_bhh  = (const float*)d_in[7];
    const float* dec_Wih  = (const float*)d_in[8];
    const float* dec_Whh  = (const float*)d_in[9];
    const float* dec_bih  = (const float*)d_in[10];
    const float* dec_bhh  = (const float*)d_in[11];
    const float* Wout     = (const float*)d_in[12];
    const float* bout     = (const float*)d_in[13];
    float* out = (float*)d_out;

    (void)in_sizes; (void)n_in;

    cudaFuncSetAttribute(k_gru_persist,
                         cudaFuncAttributeMaxDynamicSharedMemorySize, GRU_SMEM);
    cudaFuncSetAttribute(k_logits_mma,
                         cudaFuncAttributeMaxDynamicSharedMemorySize, LOGITS_SMEM);

    k_zero<<<1024, 256>>>(out);
    k_convW<<<(VV * KAB / 8 + 255) / 256, 256>>>(Wout);

    k_gates<<<dim3(24, MENC / 64), 256>>>(x, emb, enc_Wih, enc_bih, 0);
    k_gates<<<dim3(24, MDEC / 64), 256>>>(y, emb, dec_Wih, dec_bih, 1);

    k_gru_persist<<<NCTA_GRU, 256, GRU_SMEM>>>(enc_Whh, enc_bhh, dec_Whh, dec_bhh, x_lens);

    k_logits_mma<<<dim3(VV / 128, MPAD / 128), 256, LOGITS_SMEM>>>(bout, out);

    k_lse<<<MDEC, 256>>>(out);
    int has_slot = (out_size > (int)LOSS_IDX) ? 1 : 0;
    k_loss<<<1, 256>>>(out, y, out, has_slot);
}